// round 15
// baseline (speedup 1.0000x reference)
#include <cuda_runtime.h>
#include <cuda_fp16.h>
#include <math.h>
#include <stdint.h>

#define Nn 100000
#define Ee 1600000
#define HID 128
#define INDIM 256
#define NLAYERS 8
#define ALPHA 0.1f

// ---------------- scratch (device globals: no allocation allowed) -------------
__device__ int   g_is64;
__device__ int   g_cnt[Nn];
__device__ int   g_off[Nn + 1];
__device__ int   g_cur[Nn];
__device__ float g_dinv[Nn];
__device__ uint2 g_edge[Ee];                      // packed (src, w-bits)
// fp16 primary h storage
__device__ __half g_h0h[(size_t)Nn * HID];
__device__ __half g_hAh[(size_t)Nn * HID];
__device__ __half g_hBh[(size_t)Nn * HID];

__device__ __forceinline__ __half* pick_h(int id) {
    switch (id) {
        case 0: return g_h0h;
        case 1: return g_hAh;
        default: return g_hBh;
    }
}

// ---------------- dtype probe ----------------------------------------------
__global__ void k_detect(const void* ei) {
    if (threadIdx.x != 0 || blockIdx.x != 0) return;
    const long long* p64 = (const long long*)ei;
    int ok = 1;
    for (int i = 0; i < 64; i++) {
        long long v = p64[i];
        if (v < 0 || v >= Nn) { ok = 0; break; }
    }
    g_is64 = ok;
}

// ---------------- preprocessing ----------------------------------------------
__global__ void k_zero_cnt() {
    int i = blockIdx.x * blockDim.x + threadIdx.x;
    if (i < Nn) g_cnt[i] = 0;
}

__global__ void k_count(const void* __restrict__ ei) {
    int t = blockIdx.x * blockDim.x + threadIdx.x;
    int base = t * 4;
    if (base >= Ee) return;
    int c[4];
    if (g_is64) {
        const longlong2* p = (const longlong2*)((const long long*)ei + Ee);
        longlong2 a = p[t * 2], b = p[t * 2 + 1];
        c[0] = (int)a.x; c[1] = (int)a.y; c[2] = (int)b.x; c[3] = (int)b.y;
    } else {
        int4 a = ((const int4*)((const int*)ei + Ee))[t];
        c[0] = a.x; c[1] = a.y; c[2] = a.z; c[3] = a.w;
    }
    #pragma unroll
    for (int i = 0; i < 4; i++)
        if ((unsigned)c[i] < (unsigned)Nn) atomicAdd(&g_cnt[c[i]], 1);
}

// single-block shfl-scan (3 syncs/chunk) + fused dinv
__global__ void k_scan() {
    __shared__ int wsum[32];
    __shared__ int tot_s;
    __shared__ int carry_s;
    int tid  = threadIdx.x;
    int lane = tid & 31;
    int wid  = tid >> 5;
    if (tid == 0) carry_s = 0;
    __syncthreads();
    for (int base = 0; base < Nn; base += 1024) {
        int i = base + tid;
        int v = (i < Nn) ? g_cnt[i] : 0;
        int incl = v;
        #pragma unroll
        for (int o = 1; o < 32; o <<= 1) {
            int t = __shfl_up_sync(0xffffffffu, incl, o);
            if (lane >= o) incl += t;
        }
        if (lane == 31) wsum[wid] = incl;
        __syncthreads();
        if (wid == 0) {
            int s = wsum[lane];
            int si = s;
            #pragma unroll
            for (int o = 1; o < 32; o <<= 1) {
                int t = __shfl_up_sync(0xffffffffu, si, o);
                if (lane >= o) si += t;
            }
            wsum[lane] = si - s;
            if (lane == 31) tot_s = si;
        }
        __syncthreads();
        int excl = incl - v + wsum[wid] + carry_s;
        if (i < Nn) {
            g_off[i] = excl;
            g_cur[i] = excl;
            g_dinv[i] = rsqrtf((float)(v + 1));
        }
        __syncthreads();
        if (tid == 0) carry_s += tot_s;
        __syncthreads();
    }
    if (tid == 0) g_off[Nn] = carry_s;
}

__global__ void k_fill(const void* __restrict__ ei) {
    int t = blockIdx.x * blockDim.x + threadIdx.x;
    int base = t * 4;
    if (base >= Ee) return;
    int r[4], c[4];
    if (g_is64) {
        const longlong2* pr = (const longlong2*)((const long long*)ei);
        const longlong2* pc = (const longlong2*)((const long long*)ei + Ee);
        longlong2 a = pr[t * 2], b = pr[t * 2 + 1];
        r[0] = (int)a.x; r[1] = (int)a.y; r[2] = (int)b.x; r[3] = (int)b.y;
        a = pc[t * 2]; b = pc[t * 2 + 1];
        c[0] = (int)a.x; c[1] = (int)a.y; c[2] = (int)b.x; c[3] = (int)b.y;
    } else {
        int4 a = ((const int4*)((const int*)ei))[t];
        r[0] = a.x; r[1] = a.y; r[2] = a.z; r[3] = a.w;
        a = ((const int4*)((const int*)ei + Ee))[t];
        c[0] = a.x; c[1] = a.y; c[2] = a.z; c[3] = a.w;
    }
    #pragma unroll
    for (int i = 0; i < 4; i++) {
        if ((unsigned)r[i] >= (unsigned)Nn || (unsigned)c[i] >= (unsigned)Nn) continue;
        int pos = atomicAdd(&g_cur[c[i]], 1);
        float w = g_dinv[r[i]] * g_dinv[c[i]];
        g_edge[pos] = make_uint2((unsigned)r[i], __float_as_uint(w));
    }
}

// ---------------- common MMA helpers ------------------------------------------
__device__ __forceinline__ void mma_f16(float c[4], const uint32_t a[4], const uint32_t b[2]) {
    asm volatile(
        "mma.sync.aligned.m16n8k16.row.col.f32.f16.f16.f32 "
        "{%0,%1,%2,%3}, {%4,%5,%6,%7}, {%8,%9}, {%0,%1,%2,%3};"
        : "+f"(c[0]), "+f"(c[1]), "+f"(c[2]), "+f"(c[3])
        : "r"(a[0]), "r"(a[1]), "r"(a[2]), "r"(a[3]), "r"(b[0]), "r"(b[1]));
}
__device__ __forceinline__ uint32_t pack_h2(float x, float y) {
    __half2 h = __float22half2_rn(make_float2(x, y));
    return *(uint32_t*)&h;
}
__device__ __forceinline__ void ldm_x4(uint32_t r[4], uint32_t saddr) {
    asm volatile("ldmatrix.sync.aligned.m8n8.x4.shared.b16 {%0,%1,%2,%3}, [%4];"
                 : "=r"(r[0]), "=r"(r[1]), "=r"(r[2]), "=r"(r[3]) : "r"(saddr));
}
__device__ __forceinline__ void ldm_x2t(uint32_t r[2], uint32_t saddr) {
    asm volatile("ldmatrix.sync.aligned.m8n8.x2.trans.shared.b16 {%0,%1}, [%2];"
                 : "=r"(r[0]), "=r"(r[1]) : "r"(saddr));
}

// ---------------- GEMM0: h0 = relu(x @ W_in + b) -> g_h0h (fp16) --------------
__global__ void __launch_bounds__(256)
k_gemm0(const float* __restrict__ Aext,
        const float* __restrict__ W,
        const float* __restrict__ bias) {
    __shared__ __half Ash[2][128 * 32];
    __shared__ __half Bsh[2][32 * 128];

    const int K = INDIM;
    const int tid  = threadIdx.x;
    const int lane = tid & 31;
    const int wid  = tid >> 5;
    const int wm   = wid >> 2;
    const int wn   = wid & 3;
    const int rowBase = blockIdx.x * 128;

    const int ar0 = tid >> 2;
    const int ac0 = tid & 3;
    const int kp = tid >> 4;
    const int bc = tid & 15;

    float4 aR[2][2];
    float4 bR[2][2];

    #define LOAD_TILE(kb)                                                        \
        do {                                                                     \
            _Pragma("unroll")                                                    \
            for (int i = 0; i < 2; i++) {                                        \
                int gr = rowBase + ar0 + i * 64;                                 \
                aR[i][0] = make_float4(0.f,0.f,0.f,0.f);                         \
                aR[i][1] = make_float4(0.f,0.f,0.f,0.f);                         \
                if (gr < Nn) {                                                   \
                    const float* p = &Aext[(size_t)gr * K + (kb) + ac0 * 8];     \
                    aR[i][0] = *(const float4*)p;                                \
                    aR[i][1] = *(const float4*)(p + 4);                          \
                }                                                                \
            }                                                                    \
            _Pragma("unroll")                                                    \
            for (int i = 0; i < 2; i++) {                                        \
                const float* p = &W[((kb) + 2 * kp + i) * 128 + bc * 8];         \
                bR[i][0] = *(const float4*)p;                                    \
                bR[i][1] = *(const float4*)(p + 4);                              \
            }                                                                    \
        } while (0)

    #define STORE_TILE(bufi)                                                     \
        do {                                                                     \
            _Pragma("unroll")                                                    \
            for (int i = 0; i < 2; i++) {                                        \
                int R = ar0 + i * 64;                                            \
                int ce = ac0 ^ (R & 3);                                          \
                uint4 v;                                                         \
                v.x = pack_h2(aR[i][0].x, aR[i][0].y);                           \
                v.y = pack_h2(aR[i][0].z, aR[i][0].w);                           \
                v.z = pack_h2(aR[i][1].x, aR[i][1].y);                           \
                v.w = pack_h2(aR[i][1].z, aR[i][1].w);                           \
                *(uint4*)&Ash[bufi][R * 32 + ce * 8] = v;                        \
            }                                                                    \
            _Pragma("unroll")                                                    \
            for (int i = 0; i < 2; i++) {                                        \
                int k = 2 * kp + i;                                              \
                int ce = bc ^ (k & 7);                                           \
                uint4 v;                                                         \
                v.x = pack_h2(bR[i][0].x, bR[i][0].y);                           \
                v.y = pack_h2(bR[i][0].z, bR[i][0].w);                           \
                v.z = pack_h2(bR[i][1].x, bR[i][1].y);                           \
                v.w = pack_h2(bR[i][1].z, bR[i][1].w);                           \
                *(uint4*)&Bsh[bufi][k * 128 + ce * 8] = v;                       \
            }                                                                    \
        } while (0)

    LOAD_TILE(0);
    STORE_TILE(0);
    __syncthreads();

    float acc[4][4][4];
    #pragma unroll
    for (int mf = 0; mf < 4; mf++)
        #pragma unroll
        for (int nf = 0; nf < 4; nf++)
            #pragma unroll
            for (int q = 0; q < 4; q++) acc[mf][nf][q] = 0.0f;

    int buf = 0;
    for (int kb = 0; kb < K; kb += 32) {
        const bool hasNext = (kb + 32) < K;
        if (hasNext) LOAD_TILE(kb + 32);

        #pragma unroll
        for (int ks = 0; ks < 2; ks++) {
            uint32_t af[4][4];
            uint32_t bf[4][2];
            #pragma unroll
            for (int mf = 0; mf < 4; mf++) {
                int R = wm * 64 + mf * 16 + (lane & 15);
                int chunk = ks * 2 + (lane >> 4);
                int ce = chunk ^ (R & 3);
                uint32_t sa = (uint32_t)__cvta_generic_to_shared(&Ash[buf][R * 32 + ce * 8]);
                ldm_x4(af[mf], sa);
            }
            #pragma unroll
            for (int nf = 0; nf < 4; nf++) {
                int k = ks * 16 + (lane & 15);
                int chunk = wn * 4 + nf;
                int ce = chunk ^ (k & 7);
                uint32_t sb = (uint32_t)__cvta_generic_to_shared(&Bsh[buf][k * 128 + ce * 8]);
                ldm_x2t(bf[nf], sb);
            }
            #pragma unroll
            for (int mf = 0; mf < 4; mf++)
                #pragma unroll
                for (int nf = 0; nf < 4; nf++)
                    mma_f16(acc[mf][nf], af[mf], bf[nf]);
        }

        if (hasNext) {
            int nbuf = buf ^ 1;
            STORE_TILE(nbuf);
            __syncthreads();
            buf = nbuf;
        }
    }

    const int g = lane >> 2;
    const int t = lane & 3;
    #pragma unroll
    for (int mf = 0; mf < 4; mf++) {
        int row0 = rowBase + wm * 64 + mf * 16 + g;
        int row1 = row0 + 8;
        #pragma unroll
        for (int nf = 0; nf < 4; nf++) {
            int col = wn * 32 + nf * 8 + t * 2;
            float2 bb = *(const float2*)&bias[col];
            float2 v0 = make_float2(fmaxf(acc[mf][nf][0] + bb.x, 0.f),
                                    fmaxf(acc[mf][nf][1] + bb.y, 0.f));
            float2 v1 = make_float2(fmaxf(acc[mf][nf][2] + bb.x, 0.f),
                                    fmaxf(acc[mf][nf][3] + bb.y, 0.f));
            if (row0 < Nn) *(__half2*)&g_h0h[(size_t)row0 * 128 + col] = __float22half2_rn(v0);
            if (row1 < Nn) *(__half2*)&g_h0h[(size_t)row1 * 128 + col] = __float22half2_rn(v1);
        }
    }
    #undef LOAD_TILE
    #undef STORE_TILE
}

// ---------------- fused layer: agg (smem s tile) + GEMM + epilogue ------------
// 64KB smem -> 3 CTAs/SM -> enough warps in flight to hold the LTS gather roof
// (R9 retry with the occupancy bug fixed). Each warp aggregates 16 nodes into
// the swizzled fp16 Ash tile; then the standard ldmatrix GEMM runs on it.
// is_last: fused output head instead of h store.
#define G1_SMEM (128 * 128 * 2 * 2)

__global__ void __launch_bounds__(256)
k_layer(const float* __restrict__ W, float beta, int in_id, int out_id,
        int is_last, const float* __restrict__ Wout,
        const float* __restrict__ bout, float* __restrict__ outv) {
    extern __shared__ char smemraw[];
    __half* Ash = (__half*)smemraw;
    __half* Bsh = (__half*)(smemraw + 128 * 128 * 2);
    float*  Sred = (float*)Bsh;

    const int tid  = threadIdx.x;
    const int lane = tid & 31;
    const int wid  = tid >> 5;
    const int wm   = wid >> 2;
    const int wn   = wid & 3;
    const int rowBase = blockIdx.x * 128;

    // ---- stage B (W fp32 -> fp16 swizzled); independent of agg, overlaps ----
    {
        int k  = tid >> 1;
        int hf = tid & 1;
        const float* wp = &W[k * 128 + hf * 64];
        #pragma unroll
        for (int j = 0; j < 8; j++) {
            float4 f0 = *(const float4*)&wp[j * 8];
            float4 f1 = *(const float4*)&wp[j * 8 + 4];
            uint4 v;
            v.x = pack_h2(f0.x, f0.y); v.y = pack_h2(f0.z, f0.w);
            v.z = pack_h2(f1.x, f1.y); v.w = pack_h2(f1.z, f1.w);
            int chunk = hf * 8 + j;
            int ce = chunk ^ (k & 7);
            *(uint4*)&Bsh[k * 128 + ce * 8] = v;
        }
    }

    // ---- agg phase: each warp aggregates 16 nodes -> swizzled fp16 Ash ----
    const uint2* hh  = (const uint2*)pick_h(in_id);
    const uint2* h0h = (const uint2*)g_h0h;

    for (int r8 = 0; r8 < 16; r8++) {
        int R = wid * 16 + r8;
        int n = rowBase + R;
        uint2 oh = make_uint2(0u, 0u);
        if (n < Nn) {
            uint2 us  = hh[(size_t)n * 32 + lane];
            uint2 u0r = h0h[(size_t)n * 32 + lane];
            float dn = g_dinv[n];
            float sw = dn * dn;
            float2 s0 = __half22float2(*(__half2*)&us.x), s1 = __half22float2(*(__half2*)&us.y);
            float4 acc = make_float4(sw * s0.x, sw * s0.y, sw * s1.x, sw * s1.y);

            int e  = g_off[n];
            int e2 = g_off[n + 1];
            for (; e + 8 <= e2; e += 8) {
                uint2 ed[8]; uint2 u[8];
                #pragma unroll
                for (int j = 0; j < 8; j++) ed[j] = g_edge[e + j];
                #pragma unroll
                for (int j = 0; j < 8; j++)
                    u[j] = hh[(size_t)ed[j].x * 32 + lane];
                #pragma unroll
                for (int j = 0; j < 8; j++) {
                    float w = __uint_as_float(ed[j].y);
                    float2 a = __half22float2(*(__half2*)&u[j].x);
                    float2 b = __half22float2(*(__half2*)&u[j].y);
                    acc.x += w * a.x; acc.y += w * a.y;
                    acc.z += w * b.x; acc.w += w * b.y;
                }
            }
            for (; e < e2; e++) {
                uint2 ed = g_edge[e];
                float w  = __uint_as_float(ed.y);
                uint2 u  = hh[(size_t)ed.x * 32 + lane];
                float2 a = __half22float2(*(__half2*)&u.x), b = __half22float2(*(__half2*)&u.y);
                acc.x += w * a.x; acc.y += w * a.y; acc.z += w * b.x; acc.w += w * b.y;
            }

            float2 ha = __half22float2(*(__half2*)&u0r.x), hb = __half22float2(*(__half2*)&u0r.y);
            float4 sv;
            sv.x = (1.0f - ALPHA) * acc.x + ALPHA * ha.x;
            sv.y = (1.0f - ALPHA) * acc.y + ALPHA * ha.y;
            sv.z = (1.0f - ALPHA) * acc.z + ALPHA * hb.x;
            sv.w = (1.0f - ALPHA) * acc.w + ALPHA * hb.y;
            *(__half2*)&oh.x = __float22half2_rn(make_float2(sv.x, sv.y));
            *(__half2*)&oh.y = __float22half2_rn(make_float2(sv.z, sv.w));
        }
        // swizzled store: lane covers 4 halfs; chunk = lane>>1, subhalf = lane&1
        int ce = (lane >> 1) ^ (R & 7);
        *(uint2*)&Ash[R * 128 + ce * 8 + (lane & 1) * 4] = oh;
    }
    __syncthreads();

    // ---- MMA over K=128 (identical to k_gemm1) ----
    float acc[4][4][4];
    #pragma unroll
    for (int mf = 0; mf < 4; mf++)
        #pragma unroll
        for (int nf = 0; nf < 4; nf++)
            #pragma unroll
            for (int q = 0; q < 4; q++) acc[mf][nf][q] = 0.0f;

    #pragma unroll
    for (int ks = 0; ks < 8; ks++) {
        uint32_t af[4][4];
        uint32_t bf[4][2];
        #pragma unroll
        for (int mf = 0; mf < 4; mf++) {
            int R = wm * 64 + mf * 16 + (lane & 15);
            int chunk = ks * 2 + (lane >> 4);
            int ce = chunk ^ (R & 7);
            uint32_t sa = (uint32_t)__cvta_generic_to_shared(&Ash[R * 128 + ce * 8]);
            ldm_x4(af[mf], sa);
        }
        #pragma unroll
        for (int nf = 0; nf < 4; nf++) {
            int k = ks * 16 + (lane & 15);
            int chunk = wn * 4 + nf;
            int ce = chunk ^ (k & 7);
            uint32_t sb = (uint32_t)__cvta_generic_to_shared(&Bsh[k * 128 + ce * 8]);
            ldm_x2t(bf[nf], sb);
        }
        #pragma unroll
        for (int mf = 0; mf < 4; mf++)
            #pragma unroll
            for (int nf = 0; nf < 4; nf++)
                mma_f16(acc[mf][nf], af[mf], bf[nf]);
    }

    const int g = lane >> 2;
    const int t = lane & 3;

    if (!is_last) {
        __half* outh = pick_h(out_id);
        #pragma unroll
        for (int mf = 0; mf < 4; mf++) {
            int R0 = wm * 64 + mf * 16 + g;
            int R1 = R0 + 8;
            int row0 = rowBase + R0;
            int row1 = rowBase + R1;
            #pragma unroll
            for (int nf = 0; nf < 4; nf++) {
                int col = wn * 32 + nf * 8 + t * 2;
                int ch = col >> 3, ci = col & 7;
                if (row0 < Nn) {
                    int ce = ch ^ (R0 & 7);
                    float2 sv = __half22float2(*(__half2*)&Ash[R0 * 128 + ce * 8 + ci]);
                    float2 v;
                    v.x = fmaxf((1.0f - beta) * sv.x + beta * acc[mf][nf][0], 0.f);
                    v.y = fmaxf((1.0f - beta) * sv.y + beta * acc[mf][nf][1], 0.f);
                    *(__half2*)&outh[(size_t)row0 * 128 + col] = __float22half2_rn(v);
                }
                if (row1 < Nn) {
                    int ce = ch ^ (R1 & 7);
                    float2 sv = __half22float2(*(__half2*)&Ash[R1 * 128 + ce * 8 + ci]);
                    float2 v;
                    v.x = fmaxf((1.0f - beta) * sv.x + beta * acc[mf][nf][2], 0.f);
                    v.y = fmaxf((1.0f - beta) * sv.y + beta * acc[mf][nf][3], 0.f);
                    *(__half2*)&outh[(size_t)row1 * 128 + col] = __float22half2_rn(v);
                }
            }
        }
    } else {
        // ---- fused head: out[row] = relu_h(row) . Wout + bout ----
        __syncthreads();                      // Bsh ldmatrix reads done; reuse as Sred
        if (tid < 128) Sred[tid] = 0.0f;
        __syncthreads();

        #pragma unroll
        for (int mf = 0; mf < 4; mf++) {
            int R0 = wm * 64 + mf * 16 + g;
            int R1 = R0 + 8;
            float r0s = 0.f, r1s = 0.f;
            #pragma unroll
            for (int nf = 0; nf < 4; nf++) {
                int col = wn * 32 + nf * 8 + t * 2;
                int ch = col >> 3, ci = col & 7;
                float2 wv = *(const float2*)&Wout[col];
                {
                    int ce = ch ^ (R0 & 7);
                    float2 sv = __half22float2(*(__half2*)&Ash[R0 * 128 + ce * 8 + ci]);
                    float vx = fmaxf((1.0f - beta) * sv.x + beta * acc[mf][nf][0], 0.f);
                    float vy = fmaxf((1.0f - beta) * sv.y + beta * acc[mf][nf][1], 0.f);
                    r0s += vx * wv.x + vy * wv.y;
                }
                {
                    int ce = ch ^ (R1 & 7);
                    float2 sv = __half22float2(*(__half2*)&Ash[R1 * 128 + ce * 8 + ci]);
                    float vx = fmaxf((1.0f - beta) * sv.x + beta * acc[mf][nf][2], 0.f);
                    float vy = fmaxf((1.0f - beta) * sv.y + beta * acc[mf][nf][3], 0.f);
                    r1s += vx * wv.x + vy * wv.y;
                }
            }
            r0s += __shfl_xor_sync(0xffffffffu, r0s, 1);
            r0s += __shfl_xor_sync(0xffffffffu, r0s, 2);
            r1s += __shfl_xor_sync(0xffffffffu, r1s, 1);
            r1s += __shfl_xor_sync(0xffffffffu, r1s, 2);
            if (t == 0) {
                atomicAdd(&Sred[R0], r0s);
                atomicAdd(&Sred[R1], r1s);
            }
        }
        __syncthreads();
        if (tid < 128) {
            int gr = rowBase + tid;
            if (gr < Nn) outv[gr] = Sred[tid] + bout[0];
        }
    }
}

// ---------------- launch ------------------------------------------------------
extern "C" void kernel_launch(void* const* d_in, const int* in_sizes, int n_in,
                              void* d_out, int out_size) {
    const float* x     = (const float*)d_in[0];
    const void*  ei    = d_in[1];
    const float* W_in  = (const float*)d_in[2];
    const float* b_in  = (const float*)d_in[3];
    const float* convs = (const float*)d_in[4];
    const float* W_out = (const float*)d_in[5];
    const float* b_out = (const float*)d_in[6];
    float*       out   = (float*)d_out;

    (void)in_sizes; (void)n_in; (void)out_size;

    cudaFuncSetAttribute(k_layer, cudaFuncAttributeMaxDynamicSharedMemorySize, G1_SMEM);

    const int gemmGrid = (Nn + 127) / 128;   // 782

    // k_gemm0 kept at launch index 3: the fixed ncu capture slot profiles it.
    k_detect<<<1, 32>>>(ei);
    k_zero_cnt<<<(Nn + 255) / 256, 256>>>();
    k_count<<<(Ee / 4 + 255) / 256, 256>>>(ei);
    k_gemm0<<<gemmGrid, 256>>>(x, W_in, b_in);   // <- profiled slot
    k_scan<<<1, 1024>>>();                       // scan + dinv fused
    k_fill<<<(Ee / 4 + 255) / 256, 256>>>(ei);

    int cur = 0;
    for (int i = 0; i < NLAYERS; i++) {
        float beta = (float)log(0.5 / (double)(i + 1) + 1.0);
        int nxt = (i & 1) ? 2 : 1;
        int last = (i == NLAYERS - 1) ? 1 : 0;
        k_layer<<<gemmGrid, 256, G1_SMEM>>>(convs + (size_t)i * HID * HID, beta,
                                            cur, nxt, last, W_out, b_out, out);
        cur = nxt;
    }
}

// round 16
// speedup vs baseline: 1.5886x; 1.5886x over previous
#include <cuda_runtime.h>
#include <cuda_fp16.h>
#include <math.h>
#include <stdint.h>

#define Nn 100000
#define Ee 1600000
#define HID 128
#define INDIM 256
#define NLAYERS 8
#define ALPHA 0.1f

// ---------------- scratch (device globals: no allocation allowed) -------------
__device__ int   g_is64;
__device__ int   g_cnt[Nn];
__device__ int   g_off[Nn + 1];
__device__ int   g_cur[Nn];
__device__ float g_dinv[Nn];
__device__ uint2 g_edge[Ee];                      // packed (src, w-bits)
__device__ __half g_sh[(size_t)Nn * HID];         // fp16 s
__device__ __half g_Wh[NLAYERS * HID * HID];      // pre-swizzled fp16 conv weights
// fp16 primary h storage
__device__ __half g_h0h[(size_t)Nn * HID];
__device__ __half g_hAh[(size_t)Nn * HID];
__device__ __half g_hBh[(size_t)Nn * HID];

__device__ __forceinline__ __half* pick_h(int id) {
    switch (id) {
        case 0: return g_h0h;
        case 1: return g_hAh;
        default: return g_hBh;
    }
}

// ---------------- preprocessing ----------------------------------------------
// zero counters + dtype probe (merged)
__global__ void k_zero_cnt(const void* ei) {
    int i = blockIdx.x * blockDim.x + threadIdx.x;
    if (i < Nn) g_cnt[i] = 0;
    if (i == 0) {
        const long long* p64 = (const long long*)ei;
        int ok = 1;
        for (int j = 0; j < 64; j++) {
            long long v = p64[j];
            if (v < 0 || v >= Nn) { ok = 0; break; }
        }
        g_is64 = ok;
    }
}

// 8 edges per thread
__global__ void k_count(const void* __restrict__ ei) {
    int t = blockIdx.x * blockDim.x + threadIdx.x;
    if (t * 8 >= Ee) return;
    int c[8];
    if (g_is64) {
        const longlong2* p = (const longlong2*)((const long long*)ei + Ee);
        #pragma unroll
        for (int i = 0; i < 4; i++) {
            longlong2 a = p[t * 4 + i];
            c[i * 2] = (int)a.x; c[i * 2 + 1] = (int)a.y;
        }
    } else {
        const int4* p = (const int4*)((const int*)ei + Ee);
        #pragma unroll
        for (int i = 0; i < 2; i++) {
            int4 a = p[t * 2 + i];
            c[i * 4] = a.x; c[i * 4 + 1] = a.y; c[i * 4 + 2] = a.z; c[i * 4 + 3] = a.w;
        }
    }
    #pragma unroll
    for (int i = 0; i < 8; i++)
        if ((unsigned)c[i] < (unsigned)Nn) atomicAdd(&g_cnt[c[i]], 1);
}

// convert all conv weights to fp16, pre-swizzled ldmatrix layout (once)
__global__ void k_convw(const float* __restrict__ convs) {
    // each thread produces one uint4 (8 halfs) of swizzled output
    int o = blockIdx.x * blockDim.x + threadIdx.x;       // uint4 index
    if (o >= NLAYERS * HID * HID / 8) return;
    int idx = o * 8;                                     // half index
    int l   = idx / (HID * HID);
    int rem = idx % (HID * HID);
    int k   = rem >> 7;
    int ce  = (rem & 127) >> 3;
    int chunk = ce ^ (k & 7);
    const float* wp = &convs[(size_t)l * HID * HID + k * 128 + chunk * 8];
    float4 f0 = *(const float4*)wp;
    float4 f1 = *(const float4*)(wp + 4);
    uint4 v;
    __half2 h;
    h = __float22half2_rn(make_float2(f0.x, f0.y)); v.x = *(uint32_t*)&h;
    h = __float22half2_rn(make_float2(f0.z, f0.w)); v.y = *(uint32_t*)&h;
    h = __float22half2_rn(make_float2(f1.x, f1.y)); v.z = *(uint32_t*)&h;
    h = __float22half2_rn(make_float2(f1.z, f1.w)); v.w = *(uint32_t*)&h;
    ((uint4*)g_Wh)[o] = v;
}

// single-block shfl-scan (3 syncs/chunk) + fused dinv
__global__ void k_scan() {
    __shared__ int wsum[32];
    __shared__ int tot_s;
    __shared__ int carry_s;
    int tid  = threadIdx.x;
    int lane = tid & 31;
    int wid  = tid >> 5;
    if (tid == 0) carry_s = 0;
    __syncthreads();
    for (int base = 0; base < Nn; base += 1024) {
        int i = base + tid;
        int v = (i < Nn) ? g_cnt[i] : 0;
        int incl = v;
        #pragma unroll
        for (int o = 1; o < 32; o <<= 1) {
            int t = __shfl_up_sync(0xffffffffu, incl, o);
            if (lane >= o) incl += t;
        }
        if (lane == 31) wsum[wid] = incl;
        __syncthreads();
        if (wid == 0) {
            int s = wsum[lane];
            int si = s;
            #pragma unroll
            for (int o = 1; o < 32; o <<= 1) {
                int t = __shfl_up_sync(0xffffffffu, si, o);
                if (lane >= o) si += t;
            }
            wsum[lane] = si - s;
            if (lane == 31) tot_s = si;
        }
        __syncthreads();
        int excl = incl - v + wsum[wid] + carry_s;
        if (i < Nn) {
            g_off[i] = excl;
            g_cur[i] = excl;
            g_dinv[i] = rsqrtf((float)(v + 1));
        }
        __syncthreads();
        if (tid == 0) carry_s += tot_s;
        __syncthreads();
    }
    if (tid == 0) g_off[Nn] = carry_s;
}

__global__ void k_fill(const void* __restrict__ ei) {
    int t = blockIdx.x * blockDim.x + threadIdx.x;
    int base = t * 4;
    if (base >= Ee) return;
    int r[4], c[4];
    if (g_is64) {
        const longlong2* pr = (const longlong2*)((const long long*)ei);
        const longlong2* pc = (const longlong2*)((const long long*)ei + Ee);
        longlong2 a = pr[t * 2], b = pr[t * 2 + 1];
        r[0] = (int)a.x; r[1] = (int)a.y; r[2] = (int)b.x; r[3] = (int)b.y;
        a = pc[t * 2]; b = pc[t * 2 + 1];
        c[0] = (int)a.x; c[1] = (int)a.y; c[2] = (int)b.x; c[3] = (int)b.y;
    } else {
        int4 a = ((const int4*)((const int*)ei))[t];
        r[0] = a.x; r[1] = a.y; r[2] = a.z; r[3] = a.w;
        a = ((const int4*)((const int*)ei + Ee))[t];
        c[0] = a.x; c[1] = a.y; c[2] = a.z; c[3] = a.w;
    }
    #pragma unroll
    for (int i = 0; i < 4; i++) {
        if ((unsigned)r[i] >= (unsigned)Nn || (unsigned)c[i] >= (unsigned)Nn) continue;
        int pos = atomicAdd(&g_cur[c[i]], 1);
        float w = g_dinv[r[i]] * g_dinv[c[i]];
        g_edge[pos] = make_uint2((unsigned)r[i], __float_as_uint(w));
    }
}

// ---------------- common MMA helpers ------------------------------------------
__device__ __forceinline__ void mma_f16(float c[4], const uint32_t a[4], const uint32_t b[2]) {
    asm volatile(
        "mma.sync.aligned.m16n8k16.row.col.f32.f16.f16.f32 "
        "{%0,%1,%2,%3}, {%4,%5,%6,%7}, {%8,%9}, {%0,%1,%2,%3};"
        : "+f"(c[0]), "+f"(c[1]), "+f"(c[2]), "+f"(c[3])
        : "r"(a[0]), "r"(a[1]), "r"(a[2]), "r"(a[3]), "r"(b[0]), "r"(b[1]));
}
__device__ __forceinline__ uint32_t pack_h2(float x, float y) {
    __half2 h = __float22half2_rn(make_float2(x, y));
    return *(uint32_t*)&h;
}
__device__ __forceinline__ void ldm_x4(uint32_t r[4], uint32_t saddr) {
    asm volatile("ldmatrix.sync.aligned.m8n8.x4.shared.b16 {%0,%1,%2,%3}, [%4];"
                 : "=r"(r[0]), "=r"(r[1]), "=r"(r[2]), "=r"(r[3]) : "r"(saddr));
}
__device__ __forceinline__ void ldm_x2t(uint32_t r[2], uint32_t saddr) {
    asm volatile("ldmatrix.sync.aligned.m8n8.x2.trans.shared.b16 {%0,%1}, [%2];"
                 : "=r"(r[0]), "=r"(r[1]) : "r"(saddr));
}

// ---------------- aggregation: warp per node, packed edges --------------------
__global__ void k_agg(int h_id) {
    int gw   = (blockIdx.x * blockDim.x + threadIdx.x) >> 5;
    int lane = threadIdx.x & 31;
    if (gw >= Nn) return;
    int n = gw;

    const uint2* hh  = (const uint2*)pick_h(h_id);
    const uint2* h0h = (const uint2*)g_h0h;

    uint2 us  = hh[(size_t)n * 32 + lane];
    uint2 u0r = h0h[(size_t)n * 32 + lane];

    float dn = g_dinv[n];
    float sw = dn * dn;
    float2 s0 = __half22float2(*(__half2*)&us.x), s1 = __half22float2(*(__half2*)&us.y);
    float4 acc = make_float4(sw * s0.x, sw * s0.y, sw * s1.x, sw * s1.y);

    int e  = g_off[n];
    int e2 = g_off[n + 1];
    for (; e + 8 <= e2; e += 8) {
        uint2 ed[8]; uint2 u[8];
        #pragma unroll
        for (int j = 0; j < 8; j++) ed[j] = g_edge[e + j];
        #pragma unroll
        for (int j = 0; j < 8; j++)
            u[j] = hh[(size_t)ed[j].x * 32 + lane];
        #pragma unroll
        for (int j = 0; j < 8; j++) {
            float w = __uint_as_float(ed[j].y);
            float2 a = __half22float2(*(__half2*)&u[j].x);
            float2 b = __half22float2(*(__half2*)&u[j].y);
            acc.x += w * a.x; acc.y += w * a.y;
            acc.z += w * b.x; acc.w += w * b.y;
        }
    }
    for (; e < e2; e++) {
        uint2 ed = g_edge[e];
        float w  = __uint_as_float(ed.y);
        uint2 u  = hh[(size_t)ed.x * 32 + lane];
        float2 a = __half22float2(*(__half2*)&u.x), b = __half22float2(*(__half2*)&u.y);
        acc.x += w * a.x; acc.y += w * a.y; acc.z += w * b.x; acc.w += w * b.y;
    }

    float2 ha = __half22float2(*(__half2*)&u0r.x), hb = __half22float2(*(__half2*)&u0r.y);
    float4 out;
    out.x = (1.0f - ALPHA) * acc.x + ALPHA * ha.x;
    out.y = (1.0f - ALPHA) * acc.y + ALPHA * ha.y;
    out.z = (1.0f - ALPHA) * acc.z + ALPHA * hb.x;
    out.w = (1.0f - ALPHA) * acc.w + ALPHA * hb.y;
    uint2 oh;
    *(__half2*)&oh.x = __float22half2_rn(make_float2(out.x, out.y));
    *(__half2*)&oh.y = __float22half2_rn(make_float2(out.z, out.w));
    ((uint2*)g_sh)[(size_t)n * 32 + lane] = oh;
}

// ---------------- GEMM0: h0 = relu(x @ W_in + b) -> g_h0h (fp16) --------------
__global__ void __launch_bounds__(256)
k_gemm0(const float* __restrict__ Aext,
        const float* __restrict__ W,
        const float* __restrict__ bias) {
    __shared__ __half Ash[2][128 * 32];
    __shared__ __half Bsh[2][32 * 128];

    const int K = INDIM;
    const int tid  = threadIdx.x;
    const int lane = tid & 31;
    const int wid  = tid >> 5;
    const int wm   = wid >> 2;
    const int wn   = wid & 3;
    const int rowBase = blockIdx.x * 128;

    const int ar0 = tid >> 2;
    const int ac0 = tid & 3;
    const int kp = tid >> 4;
    const int bc = tid & 15;

    float4 aR[2][2];
    float4 bR[2][2];

    #define LOAD_TILE(kb)                                                        \
        do {                                                                     \
            _Pragma("unroll")                                                    \
            for (int i = 0; i < 2; i++) {                                        \
                int gr = rowBase + ar0 + i * 64;                                 \
                aR[i][0] = make_float4(0.f,0.f,0.f,0.f);                         \
                aR[i][1] = make_float4(0.f,0.f,0.f,0.f);                         \
                if (gr < Nn) {                                                   \
                    const float* p = &Aext[(size_t)gr * K + (kb) + ac0 * 8];     \
                    aR[i][0] = *(const float4*)p;                                \
                    aR[i][1] = *(const float4*)(p + 4);                          \
                }                                                                \
            }                                                                    \
            _Pragma("unroll")                                                    \
            for (int i = 0; i < 2; i++) {                                        \
                const float* p = &W[((kb) + 2 * kp + i) * 128 + bc * 8];         \
                bR[i][0] = *(const float4*)p;                                    \
                bR[i][1] = *(const float4*)(p + 4);                              \
            }                                                                    \
        } while (0)

    #define STORE_TILE(bufi)                                                     \
        do {                                                                     \
            _Pragma("unroll")                                                    \
            for (int i = 0; i < 2; i++) {                                        \
                int R = ar0 + i * 64;                                            \
                int ce = ac0 ^ (R & 3);                                          \
                uint4 v;                                                         \
                v.x = pack_h2(aR[i][0].x, aR[i][0].y);                           \
                v.y = pack_h2(aR[i][0].z, aR[i][0].w);                           \
                v.z = pack_h2(aR[i][1].x, aR[i][1].y);                           \
                v.w = pack_h2(aR[i][1].z, aR[i][1].w);                           \
                *(uint4*)&Ash[bufi][R * 32 + ce * 8] = v;                        \
            }                                                                    \
            _Pragma("unroll")                                                    \
            for (int i = 0; i < 2; i++) {                                        \
                int k = 2 * kp + i;                                              \
                int ce = bc ^ (k & 7);                                           \
                uint4 v;                                                         \
                v.x = pack_h2(bR[i][0].x, bR[i][0].y);                           \
                v.y = pack_h2(bR[i][0].z, bR[i][0].w);                           \
                v.z = pack_h2(bR[i][1].x, bR[i][1].y);                           \
                v.w = pack_h2(bR[i][1].z, bR[i][1].w);                           \
                *(uint4*)&Bsh[bufi][k * 128 + ce * 8] = v;                       \
            }                                                                    \
        } while (0)

    LOAD_TILE(0);
    STORE_TILE(0);
    __syncthreads();

    float acc[4][4][4];
    #pragma unroll
    for (int mf = 0; mf < 4; mf++)
        #pragma unroll
        for (int nf = 0; nf < 4; nf++)
            #pragma unroll
            for (int q = 0; q < 4; q++) acc[mf][nf][q] = 0.0f;

    int buf = 0;
    for (int kb = 0; kb < K; kb += 32) {
        const bool hasNext = (kb + 32) < K;
        if (hasNext) LOAD_TILE(kb + 32);

        #pragma unroll
        for (int ks = 0; ks < 2; ks++) {
            uint32_t af[4][4];
            uint32_t bf[4][2];
            #pragma unroll
            for (int mf = 0; mf < 4; mf++) {
                int R = wm * 64 + mf * 16 + (lane & 15);
                int chunk = ks * 2 + (lane >> 4);
                int ce = chunk ^ (R & 3);
                uint32_t sa = (uint32_t)__cvta_generic_to_shared(&Ash[buf][R * 32 + ce * 8]);
                ldm_x4(af[mf], sa);
            }
            #pragma unroll
            for (int nf = 0; nf < 4; nf++) {
                int k = ks * 16 + (lane & 15);
                int chunk = wn * 4 + nf;
                int ce = chunk ^ (k & 7);
                uint32_t sb = (uint32_t)__cvta_generic_to_shared(&Bsh[buf][k * 128 + ce * 8]);
                ldm_x2t(bf[nf], sb);
            }
            #pragma unroll
            for (int mf = 0; mf < 4; mf++)
                #pragma unroll
                for (int nf = 0; nf < 4; nf++)
                    mma_f16(acc[mf][nf], af[mf], bf[nf]);
        }

        if (hasNext) {
            int nbuf = buf ^ 1;
            STORE_TILE(nbuf);
            __syncthreads();
            buf = nbuf;
        }
    }

    const int g = lane >> 2;
    const int t = lane & 3;
    #pragma unroll
    for (int mf = 0; mf < 4; mf++) {
        int row0 = rowBase + wm * 64 + mf * 16 + g;
        int row1 = row0 + 8;
        #pragma unroll
        for (int nf = 0; nf < 4; nf++) {
            int col = wn * 32 + nf * 8 + t * 2;
            float2 bb = *(const float2*)&bias[col];
            float2 v0 = make_float2(fmaxf(acc[mf][nf][0] + bb.x, 0.f),
                                    fmaxf(acc[mf][nf][1] + bb.y, 0.f));
            float2 v1 = make_float2(fmaxf(acc[mf][nf][2] + bb.x, 0.f),
                                    fmaxf(acc[mf][nf][3] + bb.y, 0.f));
            if (row0 < Nn) *(__half2*)&g_h0h[(size_t)row0 * 128 + col] = __float22half2_rn(v0);
            if (row1 < Nn) *(__half2*)&g_h0h[(size_t)row1 * 128 + col] = __float22half2_rn(v1);
        }
    }
    #undef LOAD_TILE
    #undef STORE_TILE
}

// ---------------- GEMM1: h = relu((1-beta)*s + beta*(s@W)) -> fp16 ------------
// B staged by pure uint4 copy from pre-swizzled fp16 g_Wh.
// is_last==1: fused output head.
#define G1_SMEM (128 * 128 * 2 * 2)

__global__ void __launch_bounds__(256)
k_gemm1(int layer, float beta, int out_id,
        int is_last, const float* __restrict__ Wout,
        const float* __restrict__ bout, float* __restrict__ outv) {
    extern __shared__ char smemraw[];
    __half* Ash = (__half*)smemraw;
    __half* Bsh = (__half*)(smemraw + 128 * 128 * 2);
    float*  Sred = (float*)Bsh;

    const int tid  = threadIdx.x;
    const int lane = tid & 31;
    const int wid  = tid >> 5;
    const int wm   = wid >> 2;
    const int wn   = wid & 3;
    const int rowBase = blockIdx.x * 128;

    {
        int row = tid >> 1;
        int gr  = rowBase + row;
        int cbase = (tid & 1) * 8;
        #pragma unroll
        for (int j = 0; j < 8; j++) {
            int chunk = cbase + j;
            uint4 v = make_uint4(0u, 0u, 0u, 0u);
            if (gr < Nn)
                v = *(const uint4*)&g_sh[(size_t)gr * 128 + chunk * 8];
            int ce = chunk ^ (row & 7);
            *(uint4*)&Ash[row * 128 + ce * 8] = v;
        }
    }
    {
        const uint4* wsrc = (const uint4*)(g_Wh + (size_t)layer * HID * HID);
        uint4* bdst = (uint4*)Bsh;
        #pragma unroll
        for (int j = 0; j < 8; j++) {
            int idx = tid + j * 256;
            bdst[idx] = wsrc[idx];
        }
    }
    __syncthreads();

    float acc[4][4][4];
    #pragma unroll
    for (int mf = 0; mf < 4; mf++)
        #pragma unroll
        for (int nf = 0; nf < 4; nf++)
            #pragma unroll
            for (int q = 0; q < 4; q++) acc[mf][nf][q] = 0.0f;

    #pragma unroll
    for (int ks = 0; ks < 8; ks++) {
        uint32_t af[4][4];
        uint32_t bf[4][2];
        #pragma unroll
        for (int mf = 0; mf < 4; mf++) {
            int R = wm * 64 + mf * 16 + (lane & 15);
            int chunk = ks * 2 + (lane >> 4);
            int ce = chunk ^ (R & 7);
            uint32_t sa = (uint32_t)__cvta_generic_to_shared(&Ash[R * 128 + ce * 8]);
            ldm_x4(af[mf], sa);
        }
        #pragma unroll
        for (int nf = 0; nf < 4; nf++) {
            int k = ks * 16 + (lane & 15);
            int chunk = wn * 4 + nf;
            int ce = chunk ^ (k & 7);
            uint32_t sb = (uint32_t)__cvta_generic_to_shared(&Bsh[k * 128 + ce * 8]);
            ldm_x2t(bf[nf], sb);
        }
        #pragma unroll
        for (int mf = 0; mf < 4; mf++)
            #pragma unroll
            for (int nf = 0; nf < 4; nf++)
                mma_f16(acc[mf][nf], af[mf], bf[nf]);
    }

    const int g = lane >> 2;
    const int t = lane & 3;

    if (!is_last) {
        __half* outh = pick_h(out_id);
        #pragma unroll
        for (int mf = 0; mf < 4; mf++) {
            int R0 = wm * 64 + mf * 16 + g;
            int R1 = R0 + 8;
            int row0 = rowBase + R0;
            int row1 = rowBase + R1;
            #pragma unroll
            for (int nf = 0; nf < 4; nf++) {
                int col = wn * 32 + nf * 8 + t * 2;
                int ch = col >> 3, ci = col & 7;
                if (row0 < Nn) {
                    int ce = ch ^ (R0 & 7);
                    float2 sv = __half22float2(*(__half2*)&Ash[R0 * 128 + ce * 8 + ci]);
                    float2 v;
                    v.x = fmaxf((1.0f - beta) * sv.x + beta * acc[mf][nf][0], 0.f);
                    v.y = fmaxf((1.0f - beta) * sv.y + beta * acc[mf][nf][1], 0.f);
                    *(__half2*)&outh[(size_t)row0 * 128 + col] = __float22half2_rn(v);
                }
                if (row1 < Nn) {
                    int ce = ch ^ (R1 & 7);
                    float2 sv = __half22float2(*(__half2*)&Ash[R1 * 128 + ce * 8 + ci]);
                    float2 v;
                    v.x = fmaxf((1.0f - beta) * sv.x + beta * acc[mf][nf][2], 0.f);
                    v.y = fmaxf((1.0f - beta) * sv.y + beta * acc[mf][nf][3], 0.f);
                    *(__half2*)&outh[(size_t)row1 * 128 + col] = __float22half2_rn(v);
                }
            }
        }
    } else {
        // ---- fused head: out[row] = relu_h(row) . Wout + bout ----
        __syncthreads();                      // Bsh ldmatrix reads done; reuse as Sred
        if (tid < 128) Sred[tid] = 0.0f;
        __syncthreads();

        #pragma unroll
        for (int mf = 0; mf < 4; mf++) {
            int R0 = wm * 64 + mf * 16 + g;
            int R1 = R0 + 8;
            float r0s = 0.f, r1s = 0.f;
            #pragma unroll
            for (int nf = 0; nf < 4; nf++) {
                int col = wn * 32 + nf * 8 + t * 2;
                int ch = col >> 3, ci = col & 7;
                float2 wv = *(const float2*)&Wout[col];
                {
                    int ce = ch ^ (R0 & 7);
                    float2 sv = __half22float2(*(__half2*)&Ash[R0 * 128 + ce * 8 + ci]);
                    float vx = fmaxf((1.0f - beta) * sv.x + beta * acc[mf][nf][0], 0.f);
                    float vy = fmaxf((1.0f - beta) * sv.y + beta * acc[mf][nf][1], 0.f);
                    r0s += vx * wv.x + vy * wv.y;
                }
                {
                    int ce = ch ^ (R1 & 7);
                    float2 sv = __half22float2(*(__half2*)&Ash[R1 * 128 + ce * 8 + ci]);
                    float vx = fmaxf((1.0f - beta) * sv.x + beta * acc[mf][nf][2], 0.f);
                    float vy = fmaxf((1.0f - beta) * sv.y + beta * acc[mf][nf][3], 0.f);
                    r1s += vx * wv.x + vy * wv.y;
                }
            }
            r0s += __shfl_xor_sync(0xffffffffu, r0s, 1);
            r0s += __shfl_xor_sync(0xffffffffu, r0s, 2);
            r1s += __shfl_xor_sync(0xffffffffu, r1s, 1);
            r1s += __shfl_xor_sync(0xffffffffu, r1s, 2);
            if (t == 0) {
                atomicAdd(&Sred[R0], r0s);
                atomicAdd(&Sred[R1], r1s);
            }
        }
        __syncthreads();
        if (tid < 128) {
            int gr = rowBase + tid;
            if (gr < Nn) outv[gr] = Sred[tid] + bout[0];
        }
    }
}

// ---------------- launch ------------------------------------------------------
extern "C" void kernel_launch(void* const* d_in, const int* in_sizes, int n_in,
                              void* d_out, int out_size) {
    const float* x     = (const float*)d_in[0];
    const void*  ei    = d_in[1];
    const float* W_in  = (const float*)d_in[2];
    const float* b_in  = (const float*)d_in[3];
    const float* convs = (const float*)d_in[4];
    const float* W_out = (const float*)d_in[5];
    const float* b_out = (const float*)d_in[6];
    float*       out   = (float*)d_out;

    (void)in_sizes; (void)n_in; (void)out_size;

    cudaFuncSetAttribute(k_gemm1, cudaFuncAttributeMaxDynamicSharedMemorySize, G1_SMEM);

    const int gemmGrid = (Nn + 127) / 128;   // 782
    const int aggGrid  = (Nn + 7) / 8;

    // k_gemm0 kept at launch index 3: the fixed ncu capture slot profiles it.
    k_zero_cnt<<<(Nn + 255) / 256, 256>>>(ei);           // zero + dtype probe
    k_count<<<(Ee / 8 + 255) / 256, 256>>>(ei);
    k_convw<<<(NLAYERS * HID * HID / 8 + 255) / 256, 256>>>(convs);
    k_gemm0<<<gemmGrid, 256>>>(x, W_in, b_in);           // <- profiled slot
    k_scan<<<1, 1024>>>();                               // scan + dinv fused
    k_fill<<<(Ee / 4 + 255) / 256, 256>>>(ei);

    int cur = 0;
    for (int i = 0; i < NLAYERS; i++) {
        k_agg<<<aggGrid, 256>>>(cur);
        float beta = (float)log(0.5 / (double)(i + 1) + 1.0);
        int nxt = (i & 1) ? 2 : 1;
        int last = (i == NLAYERS - 1) ? 1 : 0;
        k_gemm1<<<gemmGrid, 256, G1_SMEM>>>(i, beta, nxt, last, W_out, b_out, out);
        cur = nxt;
    }
}